// round 12
// baseline (speedup 1.0000x reference)
#include <cuda_runtime.h>
#include <cuda_fp16.h>
#include <cstdint>
#include <math.h>

#define BB 8
#define CC_TOT 512
#define OO 512
#define SS 512
#define HH 64
#define WW 64
#define TAPS 9

#define EPSV 1e-8f
#define CONV_SCALE 0.014731391274719739f   // 1/sqrt(4608)
#define LIN_SCALE  0.044194173824159216f   // 1/sqrt(512)

// ---------------- device scratch (static, no allocation) ---------------------
__device__ float g_s[BB * CC_TOT];            // modulation s[b][c]
__device__ float g_mult[BB * OO];             // scale*demod[b][o]
__device__ float g_wsq[OO * CC_TOT];          // sum_k w^2 [o][c]
__device__ __align__(16) __half g_U[16 * OO * CC_TOT];                 // wino W [p][o][c]
__device__ __align__(16) __half g_V[(size_t)16 * BB * 1024 * CC_TOT];  // wino X [p*8+b][tile][c]
__device__ __align__(16) __half g_Z[(size_t)8 * BB * OO * 1024];       // j-reduced planes

// ---------------- prep: fused mod + wprep ------------------------------------
__global__ void modw_kernel(const float* __restrict__ style,
                            const float* __restrict__ mw,
                            const float* __restrict__ mb,
                            const float* __restrict__ w) {
    if (blockIdx.x < 512) {
        int wid = (blockIdx.x * 256 + threadIdx.x) >> 5;
        int lane = threadIdx.x & 31;
        int b = wid >> 9, c = wid & 511;
        float sum = 0.f;
        const float* st = style + b * SS;
        const float* mwr = mw + c * SS;
#pragma unroll 4
        for (int j = lane; j < SS; j += 32) sum += st[j] * mwr[j];
#pragma unroll
        for (int off = 16; off; off >>= 1) sum += __shfl_xor_sync(0xFFFFFFFFu, sum, off);
        if (lane == 0) g_s[b * CC_TOT + c] = sum * LIN_SCALE + mb[c];
        return;
    }
    int idx = (blockIdx.x - 512) * 256 + threadIdx.x;   // o*512 + c
    if (idx >= OO * CC_TOT) return;
    int c = idx & 511, o = idx >> 9;
    const float* wr = w + ((size_t)o * CC_TOT + c) * TAPS;
    float g[3][3];
    float sq = 0.f;
#pragma unroll
    for (int i = 0; i < 3; i++)
#pragma unroll
        for (int j = 0; j < 3; j++) {
            float v = wr[i * 3 + j];
            g[i][j] = v;
            sq += v * v;
        }
    g_wsq[o * CC_TOT + c] = sq;
    float a[4][3];
#pragma unroll
    for (int j = 0; j < 3; j++) {
        a[0][j] = g[0][j];
        a[1][j] = 0.5f * (g[0][j] + g[1][j] + g[2][j]);
        a[2][j] = 0.5f * (g[0][j] - g[1][j] + g[2][j]);
        a[3][j] = g[2][j];
    }
#pragma unroll
    for (int i = 0; i < 4; i++) {
        float u0 = a[i][0];
        float u1 = 0.5f * (a[i][0] + a[i][1] + a[i][2]);
        float u2 = 0.5f * (a[i][0] - a[i][1] + a[i][2]);
        float u3 = a[i][2];
        int p = i * 4;
        g_U[((size_t)(p + 0) * OO + o) * CC_TOT + c] = __float2half(u0);
        g_U[((size_t)(p + 1) * OO + o) * CC_TOT + c] = __float2half(u1);
        g_U[((size_t)(p + 2) * OO + o) * CC_TOT + c] = __float2half(u2);
        g_U[((size_t)(p + 3) * OO + o) * CC_TOT + c] = __float2half(u3);
    }
}

__global__ void demod_kernel() {
    int wid = (blockIdx.x * blockDim.x + threadIdx.x) >> 5;
    int lane = threadIdx.x & 31;
    int b = wid >> 9, o = wid & 511;
    float sum = 0.f;
    const float* sb = g_s + b * CC_TOT;
    const float* wq = g_wsq + o * CC_TOT;
#pragma unroll 4
    for (int j = lane; j < CC_TOT; j += 32) {
        float sv = sb[j];
        sum += wq[j] * sv * sv;
    }
#pragma unroll
    for (int off = 16; off; off >>= 1) sum += __shfl_xor_sync(0xFFFFFFFFu, sum, off);
    if (lane == 0)
        g_mult[b * OO + o] = CONV_SCALE * rsqrtf(CONV_SCALE * CONV_SCALE * sum + EPSV);
}

// ---------------- input transform: V = B^T (x*s) B -> fp16 -------------------
__global__ void __launch_bounds__(256) wino_in_kernel(const float* __restrict__ x) {
    __shared__ float ds[6][32][69];
    int cc = blockIdx.x;
    int by = blockIdx.y;          // 0..15, covers tile-rows 2by, 2by+1
    int b  = blockIdx.z;
    int tid = threadIdx.x;
    int r_glob0 = 4 * by - 1;     // global image row of ds[0]

    for (int j = tid; j < 6 * 32 * 3; j += 256) {
        int colsel = j % 3;
        int rest = j / 3;
        int c = rest & 31, hi = rest >> 5;
        ds[hi][c][colsel == 0 ? 0 : 64 + colsel] = 0.f;
    }
    if (by == 0)
        for (int j = tid; j < 32 * 69; j += 256) ds[0][j / 69][j % 69] = 0.f;
    if (by == 15)
        for (int j = tid; j < 32 * 69; j += 256) ds[5][j / 69][j % 69] = 0.f;
    __syncthreads();

    int c_l = tid >> 3, q = tid & 7;
    int c = (cc << 5) + c_l;
    float sv = g_s[b * CC_TOT + c];
    const float* xp = x + ((size_t)(b * CC_TOT + c) << 12);
#pragma unroll
    for (int hi = 0; hi < 6; hi++) {
        int h = r_glob0 + hi;
        if ((unsigned)h < (unsigned)HH) {
            const float* row = xp + (h << 6) + (q << 3);
            float* dst = &ds[hi][c_l][1 + (q << 3)];
            float4 v0 = *(const float4*)row;
            float4 v1 = *(const float4*)(row + 4);
            dst[0] = v0.x * sv; dst[1] = v0.y * sv;
            dst[2] = v0.z * sv; dst[3] = v0.w * sv;
            dst[4] = v1.x * sv; dst[5] = v1.y * sv;
            dst[6] = v1.z * sv; dst[7] = v1.w * sv;
        }
    }
    __syncthreads();

    int wwarp = tid >> 5, lane = tid & 31;
    size_t cbase = (size_t)(cc << 5) + lane;
#pragma unroll
    for (int trr = 0; trr < 2; trr++) {
        int tilerow = 2 * by + trr;
#pragma unroll
        for (int itw = 0; itw < 4; itw++) {
            int tw = wwarp * 4 + itw;
            float d[4][4];
#pragma unroll
            for (int i = 0; i < 4; i++)
#pragma unroll
                for (int j = 0; j < 4; j++)
                    d[i][j] = ds[2 * trr + i][lane][2 * tw + j];
            float t[4][4];
#pragma unroll
            for (int j = 0; j < 4; j++) {
                t[0][j] = d[0][j] - d[2][j];
                t[1][j] = d[1][j] + d[2][j];
                t[2][j] = d[2][j] - d[1][j];
                t[3][j] = d[1][j] - d[3][j];
            }
            int tile = tilerow * 32 + tw;
#pragma unroll
            for (int i = 0; i < 4; i++) {
                float v0 = t[i][0] - t[i][2];
                float v1 = t[i][1] + t[i][2];
                float v2 = t[i][2] - t[i][1];
                float v3 = t[i][1] - t[i][3];
                int p = i * 4;
                g_V[((size_t)((p + 0) * 8 + b) * 1024 + tile) * CC_TOT + cbase] = __float2half(v0);
                g_V[((size_t)((p + 1) * 8 + b) * 1024 + tile) * CC_TOT + cbase] = __float2half(v1);
                g_V[((size_t)((p + 2) * 8 + b) * 1024 + tile) * CC_TOT + cbase] = __float2half(v2);
                g_V[((size_t)((p + 3) * 8 + b) * 1024 + tile) * CC_TOT + cbase] = __float2half(v3);
            }
        }
    }
}

// ---------------- fused GEMM + j-transform -----------------------------------
// CTA 512 thr, tile 256(o) x 32(tile); z = i*8+b; loops j=0..3 sequentially
// (64 chunks of K=32). Z0 = M0+M1+M2, Z1 = M1-M2-M3 folded in registers.
#define ROWB 80
#define A_STG 20480            // 256 rows * 80
#define B_STG 2560             // 32 rows * 80
#define STG_SZ (A_STG + B_STG) // 23040
#define NSTG 4
#define GSMEM (NSTG * STG_SZ)  // 92160

__device__ __forceinline__ uint32_t smem_u32(const void* p) {
    uint32_t a;
    asm("{ .reg .u64 t; cvta.to.shared.u64 t, %1; cvt.u32.u64 %0, t; }"
        : "=r"(a) : "l"(p));
    return a;
}
#define CP_ASYNC16(dst, src) \
    asm volatile("cp.async.cg.shared.global [%0], [%1], 16;" \
                 :: "r"(dst), "l"(src) : "memory")
#define CP_COMMIT() asm volatile("cp.async.commit_group;" ::: "memory")
#define CP_WAIT(n)  asm volatile("cp.async.wait_group %0;" :: "n"(n) : "memory")
#define LDSM4(r0, r1, r2, r3, a) \
    asm volatile("ldmatrix.sync.aligned.m8n8.x4.shared.b16 {%0,%1,%2,%3}, [%4];" \
                 : "=r"(r0), "=r"(r1), "=r"(r2), "=r"(r3) : "r"(a))
#define LDSM2(r0, r1, a) \
    asm volatile("ldmatrix.sync.aligned.m8n8.x2.shared.b16 {%0,%1}, [%2];" \
                 : "=r"(r0), "=r"(r1) : "r"(a))
#define MMA16816(d0, d1, d2, d3, a0, a1, a2, a3, b0, b1) \
    asm volatile("mma.sync.aligned.m16n8k16.row.col.f32.f16.f16.f32 " \
                 "{%0,%1,%2,%3}, {%4,%5,%6,%7}, {%8,%9}, {%0,%1,%2,%3};" \
                 : "+f"(d0), "+f"(d1), "+f"(d2), "+f"(d3) \
                 : "r"(a0), "r"(a1), "r"(a2), "r"(a3), "r"(b0), "r"(b1))

__global__ void __launch_bounds__(512, 1) wino_gemm_kernel() {
    extern __shared__ __align__(16) char sm[];
    uint32_t smb = smem_u32(sm);

    int tid  = threadIdx.x;
    int wid  = tid >> 5;
    int lane = tid & 31;
    int warp_m = wid >> 2;            // 0..3 (64 o each)
    int warp_n = wid & 3;             // 0..3 (8 tiles each)

    int o_base = blockIdx.x * 256;
    int n_base = blockIdx.y * 32;
    int zi     = blockIdx.z;          // i*8 + b
    int i4     = (zi >> 3) * 4;       // p base = i*4
    int b      = zi & 7;

    float acc[4][4];                  // M fragment (one j)
    float Zr[2][4][4];                // Z0, Z1 accumulators
#pragma unroll
    for (int mi = 0; mi < 4; mi++)
#pragma unroll
        for (int k = 0; k < 4; k++) {
            acc[mi][k] = 0.f; Zr[0][mi][k] = 0.f; Zr[1][mi][k] = 0.f;
        }

    auto issue = [&](int q) {
        int j = q >> 4, cc32 = (q & 15) << 5;
        int buf = q & (NSTG - 1);
        uint32_t dA = smb + (uint32_t)buf * STG_SZ;
        uint32_t dB = dA + A_STG;
        const __half* Ab = g_U + ((size_t)(i4 + j) * OO + o_base) * CC_TOT + cc32;
        const __half* Bb = g_V + ((size_t)((i4 + j) * 8 + b) * 1024 + n_base) * CC_TOT + cc32;
        // A: 256 rows x 64B = 1024 16B-units; 2 per thread (contiguous pair)
#pragma unroll
        for (int u2 = 0; u2 < 2; u2++) {
            int u = tid * 2 + u2;
            int row = u >> 2, seg = u & 3;
            CP_ASYNC16(dA + (uint32_t)(row * ROWB + seg * 16),
                       (const char*)(Ab + (size_t)row * CC_TOT + seg * 8));
        }
        // B: 32 rows x 64B = 128 units; threads 0..127
        if (tid < 128) {
            int row = tid >> 2, seg = tid & 3;
            CP_ASYNC16(dB + (uint32_t)(row * ROWB + seg * 16),
                       (const char*)(Bb + (size_t)row * CC_TOT + seg * 8));
        }
        CP_COMMIT();
    };

    uint32_t a_off = (uint32_t)((warp_m * 64 + (lane & 15)) * ROWB + (lane >> 4) * 16);
    uint32_t b_off = (uint32_t)((warp_n * 8 + (lane & 7)) * ROWB + ((lane >> 3) & 1) * 16);

    issue(0); issue(1); issue(2);

#pragma unroll 1
    for (int q = 0; q < 64; q++) {
        if (q < 61)       { CP_WAIT(2); }
        else if (q == 61) { CP_WAIT(1); }
        else              { CP_WAIT(0); }
        __syncthreads();

        int buf = q & (NSTG - 1);
        uint32_t sA = smb + (uint32_t)buf * STG_SZ;
        uint32_t sB = sA + A_STG;

#pragma unroll
        for (int ks = 0; ks < 2; ks++) {
            uint32_t koff = ks * 32;
            uint32_t a[4][4], b0, b1;
            LDSM2(b0, b1, sB + b_off + koff);
#pragma unroll
            for (int mi = 0; mi < 4; mi++)
                LDSM4(a[mi][0], a[mi][1], a[mi][2], a[mi][3],
                      sA + a_off + (uint32_t)(mi * 16 * ROWB) + koff);
#pragma unroll
            for (int mi = 0; mi < 4; mi++)
                MMA16816(acc[mi][0], acc[mi][1], acc[mi][2], acc[mi][3],
                         a[mi][0], a[mi][1], a[mi][2], a[mi][3], b0, b1);
        }
        if (q + 3 < 64) issue(q + 3);

        // j-boundary: fold M_j into Z and reset acc
        if ((q & 15) == 15) {
            int j = q >> 4;
#pragma unroll
            for (int mi = 0; mi < 4; mi++)
#pragma unroll
                for (int k = 0; k < 4; k++) {
                    float v = acc[mi][k];
                    if (j == 0)      { Zr[0][mi][k] += v; }
                    else if (j == 1) { Zr[0][mi][k] += v; Zr[1][mi][k] += v; }
                    else if (j == 2) { Zr[0][mi][k] += v; Zr[1][mi][k] -= v; }
                    else             { Zr[1][mi][k] -= v; }
                    acc[mi][k] = 0.f;
                }
        }
    }

    // epilogue: write Z planes fp16. plane = (i*2+v)*8 + b
#pragma unroll
    for (int v = 0; v < 2; v++) {
        __half* Zb = g_Z + ((size_t)(((i4 >> 2) * 2 + v) * 8 + b) * OO) * 1024;
#pragma unroll
        for (int mi = 0; mi < 4; mi++) {
#pragma unroll
            for (int hf = 0; hf < 2; hf++) {
                int o = o_base + warp_m * 64 + mi * 16 + (lane >> 2) + hf * 8;
                int tile = n_base + warp_n * 8 + (lane & 3) * 2;
                *(__half2*)(Zb + (size_t)o * 1024 + tile) =
                    __floats2half2_rn(Zr[v][mi][hf * 2 + 0], Zr[v][mi][hf * 2 + 1]);
            }
        }
    }
}

// ---------------- output transform: i-direction combos + demod ---------------
__global__ void __launch_bounds__(256) wino_out_kernel(float* __restrict__ out) {
    int bo = blockIdx.x;                 // b*512 + o
    int b = bo >> 9, o = bo & 511;
    int tid = threadIdx.x;
    float m = g_mult[bo];
    int t0 = tid << 2;                   // 4 tiles per thread

    float z[4][2][4];                    // [i][v][tile]
#pragma unroll
    for (int i = 0; i < 4; i++)
#pragma unroll
        for (int v = 0; v < 2; v++) {
            const __half2* src = (const __half2*)
                &g_Z[((size_t)((i * 2 + v) * 8 + b) * OO + o) * 1024 + t0];
            float2 f0 = __half22float2(src[0]);
            float2 f1 = __half22float2(src[1]);
            z[i][v][0] = f0.x; z[i][v][1] = f0.y;
            z[i][v][2] = f1.x; z[i][v][3] = f1.y;
        }

    int trr = t0 >> 5, tww = t0 & 31;
    float* op = out + (((size_t)bo) << 12) + (trr * 2) * 64 + tww * 2;
    float4 r0a, r0b, r1a, r1b;
#pragma unroll
    for (int t = 0; t < 4; t++) {
        float y00 = (z[0][0][t] + z[1][0][t] + z[2][0][t]) * m;
        float y01 = (z[0][1][t] + z[1][1][t] + z[2][1][t]) * m;
        float y10 = (z[1][0][t] - z[2][0][t] - z[3][0][t]) * m;
        float y11 = (z[1][1][t] - z[2][1][t] - z[3][1][t]) * m;
        if (t < 2) {
            ((float2*)&r0a)[t] = make_float2(y00, y01);
            ((float2*)&r1a)[t] = make_float2(y10, y11);
        } else {
            ((float2*)&r0b)[t - 2] = make_float2(y00, y01);
            ((float2*)&r1b)[t - 2] = make_float2(y10, y11);
        }
    }
    *(float4*)op = r0a;
    *(float4*)(op + 4) = r0b;
    *(float4*)(op + 64) = r1a;
    *(float4*)(op + 68) = r1b;
}

// ---------------- launch -----------------------------------------------------
extern "C" void kernel_launch(void* const* d_in, const int* in_sizes, int n_in,
                              void* d_out, int out_size) {
    const float* input  = (const float*)d_in[0];   // [B,C,H,W]
    const float* style  = (const float*)d_in[1];   // [B,S]
    const float* weight = (const float*)d_in[2];   // [1,O,C,3,3]
    const float* mw     = (const float*)d_in[3];   // [C,S]
    const float* mb     = (const float*)d_in[4];   // [C]
    float* out = (float*)d_out;

    modw_kernel<<<512 + 1024, 256>>>(style, mw, mb, weight);
    demod_kernel<<<512, 256>>>();
    {
        dim3 gi(16, 16, 8);
        wino_in_kernel<<<gi, 256>>>(input);
    }
    cudaFuncSetAttribute(wino_gemm_kernel,
                         cudaFuncAttributeMaxDynamicSharedMemorySize, GSMEM);
    {
        dim3 gg(2, 32, 32);   // (o-tiles, n-tiles, i*8+b)
        wino_gemm_kernel<<<gg, 512, GSMEM>>>();
    }
    wino_out_kernel<<<4096, 256>>>(out);
}

// round 13
// speedup vs baseline: 1.7199x; 1.7199x over previous
#include <cuda_runtime.h>
#include <cuda_fp16.h>
#include <cstdint>
#include <math.h>

#define BB 8
#define CC_TOT 512
#define OO 512
#define SS 512
#define HH 64
#define WW 64
#define TAPS 9

#define EPSV 1e-8f
#define CONV_SCALE 0.014731391274719739f   // 1/sqrt(4608)
#define LIN_SCALE  0.044194173824159216f   // 1/sqrt(512)

// ---------------- device scratch (static, no allocation) ---------------------
__device__ float g_s[BB * CC_TOT];            // modulation s[b][c]
__device__ float g_mult[BB * OO];             // scale*demod[b][o]
__device__ float g_wsq[OO * CC_TOT];          // sum_k w^2 [o][c]
__device__ __align__(16) __half g_U[16 * OO * CC_TOT];                 // wino W [p][o][c]
__device__ __align__(16) __half g_V[(size_t)16 * BB * 1024 * CC_TOT];  // wino X [p*8+b][tile][c]
__device__ __align__(16) __half g_Mh[(size_t)16 * BB * OO * 1024];     // GEMM out fp16

// ---------------- prep kernels ----------------------------------------------
__global__ void mod_kernel(const float* __restrict__ style,
                           const float* __restrict__ mw,
                           const float* __restrict__ mb) {
    int wid = (blockIdx.x * blockDim.x + threadIdx.x) >> 5;
    int lane = threadIdx.x & 31;
    int b = wid >> 9, c = wid & 511;
    float sum = 0.f;
    const float* st = style + b * SS;
    const float* mwr = mw + c * SS;
#pragma unroll 4
    for (int j = lane; j < SS; j += 32) sum += st[j] * mwr[j];
#pragma unroll
    for (int off = 16; off; off >>= 1) sum += __shfl_xor_sync(0xFFFFFFFFu, sum, off);
    if (lane == 0) g_s[b * CC_TOT + c] = sum * LIN_SCALE + mb[c];
}

// weight: wsq + Winograd transform U = G g G^T  -> fp16 [p][o][c]
__global__ void wprep_kernel(const float* __restrict__ w) {
    int idx = blockIdx.x * blockDim.x + threadIdx.x;   // o*512 + c
    if (idx >= OO * CC_TOT) return;
    int c = idx & 511, o = idx >> 9;
    const float* wr = w + ((size_t)o * CC_TOT + c) * TAPS;
    float g[3][3];
    float sq = 0.f;
#pragma unroll
    for (int i = 0; i < 3; i++)
#pragma unroll
        for (int j = 0; j < 3; j++) {
            float v = wr[i * 3 + j];
            g[i][j] = v;
            sq += v * v;
        }
    g_wsq[o * CC_TOT + c] = sq;
    float a[4][3];
#pragma unroll
    for (int j = 0; j < 3; j++) {
        a[0][j] = g[0][j];
        a[1][j] = 0.5f * (g[0][j] + g[1][j] + g[2][j]);
        a[2][j] = 0.5f * (g[0][j] - g[1][j] + g[2][j]);
        a[3][j] = g[2][j];
    }
#pragma unroll
    for (int i = 0; i < 4; i++) {
        float u0 = a[i][0];
        float u1 = 0.5f * (a[i][0] + a[i][1] + a[i][2]);
        float u2 = 0.5f * (a[i][0] - a[i][1] + a[i][2]);
        float u3 = a[i][2];
        int p = i * 4;
        g_U[((size_t)(p + 0) * OO + o) * CC_TOT + c] = __float2half(u0);
        g_U[((size_t)(p + 1) * OO + o) * CC_TOT + c] = __float2half(u1);
        g_U[((size_t)(p + 2) * OO + o) * CC_TOT + c] = __float2half(u2);
        g_U[((size_t)(p + 3) * OO + o) * CC_TOT + c] = __float2half(u3);
    }
}

__global__ void demod_kernel() {
    int wid = (blockIdx.x * blockDim.x + threadIdx.x) >> 5;
    int lane = threadIdx.x & 31;
    int b = wid >> 9, o = wid & 511;
    float sum = 0.f;
    const float* sb = g_s + b * CC_TOT;
    const float* wq = g_wsq + o * CC_TOT;
#pragma unroll 4
    for (int j = lane; j < CC_TOT; j += 32) {
        float sv = sb[j];
        sum += wq[j] * sv * sv;
    }
#pragma unroll
    for (int off = 16; off; off >>= 1) sum += __shfl_xor_sync(0xFFFFFFFFu, sum, off);
    if (lane == 0)
        g_mult[b * OO + o] = CONV_SCALE * rsqrtf(CONV_SCALE * CONV_SCALE * sum + EPSV);
}

// ---------------- input transform: V = B^T (x*s) B -> fp16 -------------------
// Block: 2 tile-rows sharing a 6-row halo.
__global__ void __launch_bounds__(256) wino_in_kernel(const float* __restrict__ x) {
    __shared__ float ds[6][32][69];
    int cc = blockIdx.x;
    int by = blockIdx.y;          // 0..15, covers tile-rows 2by, 2by+1
    int b  = blockIdx.z;
    int tid = threadIdx.x;
    int r_glob0 = 4 * by - 1;     // global image row of ds[0]

    for (int j = tid; j < 6 * 32 * 3; j += 256) {
        int colsel = j % 3;
        int rest = j / 3;
        int c = rest & 31, hi = rest >> 5;
        ds[hi][c][colsel == 0 ? 0 : 64 + colsel] = 0.f;
    }
    if (by == 0)
        for (int j = tid; j < 32 * 69; j += 256) ds[0][j / 69][j % 69] = 0.f;
    if (by == 15)
        for (int j = tid; j < 32 * 69; j += 256) ds[5][j / 69][j % 69] = 0.f;
    __syncthreads();

    int c_l = tid >> 3, q = tid & 7;        // c 0..31, 8-float segment
    int c = (cc << 5) + c_l;
    float sv = g_s[b * CC_TOT + c];
    const float* xp = x + ((size_t)(b * CC_TOT + c) << 12);
#pragma unroll
    for (int hi = 0; hi < 6; hi++) {
        int h = r_glob0 + hi;
        if ((unsigned)h < (unsigned)HH) {
            const float* row = xp + (h << 6) + (q << 3);
            float* dst = &ds[hi][c_l][1 + (q << 3)];
            float4 v0 = *(const float4*)row;
            float4 v1 = *(const float4*)(row + 4);
            dst[0] = v0.x * sv; dst[1] = v0.y * sv;
            dst[2] = v0.z * sv; dst[3] = v0.w * sv;
            dst[4] = v1.x * sv; dst[5] = v1.y * sv;
            dst[6] = v1.z * sv; dst[7] = v1.w * sv;
        }
    }
    __syncthreads();

    int wwarp = tid >> 5, lane = tid & 31;
    size_t cbase = (size_t)(cc << 5) + lane;
#pragma unroll
    for (int trr = 0; trr < 2; trr++) {
        int tilerow = 2 * by + trr;
#pragma unroll
        for (int itw = 0; itw < 4; itw++) {
            int tw = wwarp * 4 + itw;
            float d[4][4];
#pragma unroll
            for (int i = 0; i < 4; i++)
#pragma unroll
                for (int j = 0; j < 4; j++)
                    d[i][j] = ds[2 * trr + i][lane][2 * tw + j];
            float t[4][4];
#pragma unroll
            for (int j = 0; j < 4; j++) {
                t[0][j] = d[0][j] - d[2][j];
                t[1][j] = d[1][j] + d[2][j];
                t[2][j] = d[2][j] - d[1][j];
                t[3][j] = d[1][j] - d[3][j];
            }
            int tile = tilerow * 32 + tw;
#pragma unroll
            for (int i = 0; i < 4; i++) {
                float v0 = t[i][0] - t[i][2];
                float v1 = t[i][1] + t[i][2];
                float v2 = t[i][2] - t[i][1];
                float v3 = t[i][1] - t[i][3];
                int p = i * 4;
                g_V[((size_t)((p + 0) * 8 + b) * 1024 + tile) * CC_TOT + cbase] = __float2half(v0);
                g_V[((size_t)((p + 1) * 8 + b) * 1024 + tile) * CC_TOT + cbase] = __float2half(v1);
                g_V[((size_t)((p + 2) * 8 + b) * 1024 + tile) * CC_TOT + cbase] = __float2half(v2);
                g_V[((size_t)((p + 3) * 8 + b) * 1024 + tile) * CC_TOT + cbase] = __float2half(v3);
            }
        }
    }
}

// ---------------- persistent batched GEMM: Mh[z] = U[z>>3] * V[z]^T ----------
// 296 persistent CTAs (2/SM), 256 thr, tile 128x128. Work w = bid + 296k;
// 16 K-chunks per work; 4-stage cp.async pipeline continuous across works.
#define ROWB 80
#define ABUF 10240
#define NSTG 4
#define GSMEM (2 * NSTG * ABUF)   // 81920
#define NWORK 4096
#define PCTAS 296

__device__ __forceinline__ uint32_t smem_u32(const void* p) {
    uint32_t a;
    asm("{ .reg .u64 t; cvta.to.shared.u64 t, %1; cvt.u32.u64 %0, t; }"
        : "=r"(a) : "l"(p));
    return a;
}
#define CP_ASYNC16(dst, src) \
    asm volatile("cp.async.cg.shared.global [%0], [%1], 16;" \
                 :: "r"(dst), "l"(src) : "memory")
#define CP_COMMIT() asm volatile("cp.async.commit_group;" ::: "memory")
#define CP_WAIT(n)  asm volatile("cp.async.wait_group %0;" :: "n"(n) : "memory")
#define LDSM4(r0, r1, r2, r3, a) \
    asm volatile("ldmatrix.sync.aligned.m8n8.x4.shared.b16 {%0,%1,%2,%3}, [%4];" \
                 : "=r"(r0), "=r"(r1), "=r"(r2), "=r"(r3) : "r"(a))
#define MMA16816(d0, d1, d2, d3, a0, a1, a2, a3, b0, b1) \
    asm volatile("mma.sync.aligned.m16n8k16.row.col.f32.f16.f16.f32 " \
                 "{%0,%1,%2,%3}, {%4,%5,%6,%7}, {%8,%9}, {%0,%1,%2,%3};" \
                 : "+f"(d0), "+f"(d1), "+f"(d2), "+f"(d3) \
                 : "r"(a0), "r"(a1), "r"(a2), "r"(a3), "r"(b0), "r"(b1))

__global__ void __launch_bounds__(256, 2) wino_gemm_kernel() {
    extern __shared__ __align__(16) char sm[];   // A0..A3 B0..B3
    uint32_t smb = smem_u32(sm);

    int tid  = threadIdx.x;
    int wid  = tid >> 5;
    int lane = tid & 31;
    int warp_m = wid >> 2;            // 0..1 (64 o)
    int warp_n = wid & 3;             // 0..3 (32 tiles)
    int bid  = blockIdx.x;

    int nw = (NWORK - bid + PCTAS - 1) / PCTAS;   // works for this CTA
    int T  = nw << 4;                              // total chunks

    float acc[4][4][4];
#pragma unroll
    for (int i = 0; i < 4; i++)
#pragma unroll
        for (int j = 0; j < 4; j++)
#pragma unroll
            for (int k = 0; k < 4; k++) acc[i][j][k] = 0.f;

    int f_row = tid >> 1;
    // issue fills for global chunk q: work = bid + 296*(q>>4), chunk = q&15
    auto issue = [&](int q) {
        int w  = bid + PCTAS * (q >> 4);
        int ob = (w & 3) << 7;          // o_base
        int nb = ((w >> 2) & 7) << 7;   // n_base
        int z  = w >> 5;
        int c0 = (q & 15) << 5;
        int buf = q & (NSTG - 1);
        uint32_t dA = smb + (uint32_t)buf * ABUF;
        uint32_t dB = smb + NSTG * ABUF + (uint32_t)buf * ABUF;
        const __half* sa = g_U + ((size_t)(z >> 3) * OO + ob + f_row) * CC_TOT + c0;
        const __half* sb = g_V + ((size_t)z * 1024 + nb + f_row) * CC_TOT + c0;
#pragma unroll
        for (int u = 0; u < 2; u++) {
            int unit = (tid & 1) * 2 + u;
            CP_ASYNC16(dA + (uint32_t)(f_row * ROWB + unit * 16),
                       (const char*)(sa + unit * 8));
            CP_ASYNC16(dB + (uint32_t)(f_row * ROWB + unit * 16),
                       (const char*)(sb + unit * 8));
        }
        CP_COMMIT();
    };

    uint32_t a_off = (uint32_t)((warp_m * 64 + (lane & 15)) * ROWB + (lane >> 4) * 16);
    uint32_t b_off = (uint32_t)((warp_n * 32 + (lane & 15)) * ROWB + (lane >> 4) * 16);

    issue(0); issue(1); issue(2);

#pragma unroll 1
    for (int q = 0; q < T; q++) {
        // group q must be complete; outstanding ≤ {q+1, q+2}
        if (q <= T - 3)      { CP_WAIT(2); }
        else if (q == T - 2) { CP_WAIT(1); }
        else                 { CP_WAIT(0); }
        __syncthreads();

        int buf = q & (NSTG - 1);
        uint32_t sA = smb + (uint32_t)buf * ABUF;
        uint32_t sB = smb + NSTG * ABUF + (uint32_t)buf * ABUF;

#pragma unroll
        for (int ks = 0; ks < 2; ks++) {
            uint32_t koff = ks * 32;
            uint32_t a[4][4], bm[2][4];
#pragma unroll
            for (int mi = 0; mi < 4; mi++)
                LDSM4(a[mi][0], a[mi][1], a[mi][2], a[mi][3],
                      sA + a_off + (uint32_t)(mi * 16 * ROWB) + koff);
#pragma unroll
            for (int ni = 0; ni < 2; ni++)
                LDSM4(bm[ni][0], bm[ni][1], bm[ni][2], bm[ni][3],
                      sB + b_off + (uint32_t)(ni * 16 * ROWB) + koff);
#pragma unroll
            for (int mi = 0; mi < 4; mi++) {
#pragma unroll
                for (int ni = 0; ni < 2; ni++) {
                    MMA16816(acc[mi][ni * 2][0], acc[mi][ni * 2][1],
                             acc[mi][ni * 2][2], acc[mi][ni * 2][3],
                             a[mi][0], a[mi][1], a[mi][2], a[mi][3],
                             bm[ni][0], bm[ni][2]);
                    MMA16816(acc[mi][ni * 2 + 1][0], acc[mi][ni * 2 + 1][1],
                             acc[mi][ni * 2 + 1][2], acc[mi][ni * 2 + 1][3],
                             a[mi][0], a[mi][1], a[mi][2], a[mi][3],
                             bm[ni][1], bm[ni][3]);
                }
            }
        }
        // keep pipeline streaming into the next tile's chunks
        if (q + 3 < T) issue(q + 3);

        // end of a work item: write fp16 M fragment, reset acc
        if ((q & 15) == 15) {
            int w  = bid + PCTAS * (q >> 4);
            int ob = (w & 3) << 7;
            int nb = ((w >> 2) & 7) << 7;
            int z  = w >> 5;
            __half* Mb = g_Mh + (size_t)z * OO * 1024;
#pragma unroll
            for (int mi = 0; mi < 4; mi++) {
#pragma unroll
                for (int hf = 0; hf < 2; hf++) {
                    int o = ob + warp_m * 64 + mi * 16 + (lane >> 2) + hf * 8;
                    __half2* op = (__half2*)(Mb + (size_t)o * 1024 + nb +
                                             warp_n * 32 + (lane & 3) * 2);
#pragma unroll
                    for (int ni = 0; ni < 4; ni++) {
                        op[ni * 4] = __floats2half2_rn(acc[mi][ni][hf * 2 + 0],
                                                       acc[mi][ni][hf * 2 + 1]);
                        acc[mi][ni][hf * 2 + 0] = 0.f;
                        acc[mi][ni][hf * 2 + 1] = 0.f;
                    }
                }
            }
        }
    }
}

// ---------------- output transform: out = A^T M A * demod --------------------
__global__ void __launch_bounds__(256) wino_out_kernel(float* __restrict__ out) {
    int bo = blockIdx.x;                 // b*512 + o
    int b = bo >> 9, o = bo & 511;
    int tid = threadIdx.x;
    float m = g_mult[bo];
    int t0 = tid << 2;                   // 4 tiles per thread

    float M4[16][4];
#pragma unroll
    for (int p = 0; p < 16; p++) {
        const __half2* src =
            (const __half2*)&g_Mh[((size_t)(p * 8 + b) * OO + o) * 1024 + t0];
        float2 f0 = __half22float2(src[0]);
        float2 f1 = __half22float2(src[1]);
        M4[p][0] = f0.x; M4[p][1] = f0.y; M4[p][2] = f1.x; M4[p][3] = f1.y;
    }

    int trr = t0 >> 5, tww = t0 & 31;
    float* op = out + (((size_t)bo) << 12) + (trr * 2) * 64 + tww * 2;
    float4 r0a, r0b, r1a, r1b;
#pragma unroll
    for (int j = 0; j < 4; j++) {
        float M[4][4];
#pragma unroll
        for (int p = 0; p < 16; p++)
            M[p >> 2][p & 3] = M4[p][j];
        float t0r[4], t1r[4];
#pragma unroll
        for (int k = 0; k < 4; k++) {
            t0r[k] = M[0][k] + M[1][k] + M[2][k];
            t1r[k] = M[1][k] - M[2][k] - M[3][k];
        }
        float y00 = (t0r[0] + t0r[1] + t0r[2]) * m;
        float y01 = (t0r[1] - t0r[2] - t0r[3]) * m;
        float y10 = (t1r[0] + t1r[1] + t1r[2]) * m;
        float y11 = (t1r[1] - t1r[2] - t1r[3]) * m;
        if (j < 2) {
            ((float2*)&r0a)[j] = make_float2(y00, y01);
            ((float2*)&r1a)[j] = make_float2(y10, y11);
        } else {
            ((float2*)&r0b)[j - 2] = make_float2(y00, y01);
            ((float2*)&r1b)[j - 2] = make_float2(y10, y11);
        }
    }
    *(float4*)op = r0a;
    *(float4*)(op + 4) = r0b;
    *(float4*)(op + 64) = r1a;
    *(float4*)(op + 68) = r1b;
}

// ---------------- launch -----------------------------------------------------
extern "C" void kernel_launch(void* const* d_in, const int* in_sizes, int n_in,
                              void* d_out, int out_size) {
    const float* input  = (const float*)d_in[0];   // [B,C,H,W]
    const float* style  = (const float*)d_in[1];   // [B,S]
    const float* weight = (const float*)d_in[2];   // [1,O,C,3,3]
    const float* mw     = (const float*)d_in[3];   // [C,S]
    const float* mb     = (const float*)d_in[4];   // [C]
    float* out = (float*)d_out;

    mod_kernel<<<512, 256>>>(style, mw, mb);
    wprep_kernel<<<(OO * CC_TOT + 255) / 256, 256>>>(weight);
    demod_kernel<<<512, 256>>>();
    {
        dim3 gi(16, 16, 8);
        wino_in_kernel<<<gi, 256>>>(input);
    }
    cudaFuncSetAttribute(wino_gemm_kernel,
                         cudaFuncAttributeMaxDynamicSharedMemorySize, GSMEM);
    wino_gemm_kernel<<<PCTAS, 256, GSMEM>>>();
    wino_out_kernel<<<4096, 256>>>(out);
}

// round 14
// speedup vs baseline: 1.8661x; 1.0850x over previous
#include <cuda_runtime.h>
#include <cuda_fp16.h>
#include <cstdint>
#include <math.h>

#define BB 8
#define CC_TOT 512
#define OO 512
#define SS 512
#define HH 64
#define WW 64
#define TAPS 9

#define EPSV 1e-8f
#define CONV_SCALE 0.014731391274719739f   // 1/sqrt(4608)
#define LIN_SCALE  0.044194173824159216f   // 1/sqrt(512)

// ---------------- device scratch (static, no allocation) ---------------------
__device__ float g_s[BB * CC_TOT];            // modulation s[b][c]
__device__ float g_mult[BB * OO];             // scale*demod[b][o]
__device__ float g_wsq[OO * CC_TOT];          // sum_k w^2 [o][c]
__device__ __align__(16) __half g_U[16 * OO * CC_TOT];                 // wino W [p][o][c]
__device__ __align__(16) __half g_V[(size_t)16 * BB * 1024 * CC_TOT];  // wino X [p*8+b][tile][c]
__device__ __align__(16) __half g_Mh[(size_t)16 * BB * OO * 1024];     // GEMM out fp16

// ---------------- prep: fused mod + wprep (independent halves) ---------------
__global__ void modw_kernel(const float* __restrict__ style,
                            const float* __restrict__ mw,
                            const float* __restrict__ mb,
                            const float* __restrict__ w) {
    if (blockIdx.x < 512) {
        int wid = (blockIdx.x * 256 + threadIdx.x) >> 5;
        int lane = threadIdx.x & 31;
        int b = wid >> 9, c = wid & 511;
        float sum = 0.f;
        const float* st = style + b * SS;
        const float* mwr = mw + c * SS;
#pragma unroll 4
        for (int j = lane; j < SS; j += 32) sum += st[j] * mwr[j];
#pragma unroll
        for (int off = 16; off; off >>= 1) sum += __shfl_xor_sync(0xFFFFFFFFu, sum, off);
        if (lane == 0) g_s[b * CC_TOT + c] = sum * LIN_SCALE + mb[c];
        return;
    }
    int idx = (blockIdx.x - 512) * 256 + threadIdx.x;   // o*512 + c
    if (idx >= OO * CC_TOT) return;
    int c = idx & 511, o = idx >> 9;
    const float* wr = w + ((size_t)o * CC_TOT + c) * TAPS;
    float g[3][3];
    float sq = 0.f;
#pragma unroll
    for (int i = 0; i < 3; i++)
#pragma unroll
        for (int j = 0; j < 3; j++) {
            float v = wr[i * 3 + j];
            g[i][j] = v;
            sq += v * v;
        }
    g_wsq[o * CC_TOT + c] = sq;
    float a[4][3];
#pragma unroll
    for (int j = 0; j < 3; j++) {
        a[0][j] = g[0][j];
        a[1][j] = 0.5f * (g[0][j] + g[1][j] + g[2][j]);
        a[2][j] = 0.5f * (g[0][j] - g[1][j] + g[2][j]);
        a[3][j] = g[2][j];
    }
#pragma unroll
    for (int i = 0; i < 4; i++) {
        float u0 = a[i][0];
        float u1 = 0.5f * (a[i][0] + a[i][1] + a[i][2]);
        float u2 = 0.5f * (a[i][0] - a[i][1] + a[i][2]);
        float u3 = a[i][2];
        int p = i * 4;
        g_U[((size_t)(p + 0) * OO + o) * CC_TOT + c] = __float2half(u0);
        g_U[((size_t)(p + 1) * OO + o) * CC_TOT + c] = __float2half(u1);
        g_U[((size_t)(p + 2) * OO + o) * CC_TOT + c] = __float2half(u2);
        g_U[((size_t)(p + 3) * OO + o) * CC_TOT + c] = __float2half(u3);
    }
}

__global__ void demod_kernel() {
    int wid = (blockIdx.x * blockDim.x + threadIdx.x) >> 5;
    int lane = threadIdx.x & 31;
    int b = wid >> 9, o = wid & 511;
    float sum = 0.f;
    const float* sb = g_s + b * CC_TOT;
    const float* wq = g_wsq + o * CC_TOT;
#pragma unroll 4
    for (int j = lane; j < CC_TOT; j += 32) {
        float sv = sb[j];
        sum += wq[j] * sv * sv;
    }
#pragma unroll
    for (int off = 16; off; off >>= 1) sum += __shfl_xor_sync(0xFFFFFFFFu, sum, off);
    if (lane == 0)
        g_mult[b * OO + o] = CONV_SCALE * rsqrtf(CONV_SCALE * CONV_SCALE * sum + EPSV);
}

// ---------------- input transform: V = B^T (x*s) B -> fp16 -------------------
// Block: 2 tile-rows sharing a 6-row halo.
__global__ void __launch_bounds__(256) wino_in_kernel(const float* __restrict__ x) {
    __shared__ float ds[6][32][69];
    int cc = blockIdx.x;
    int by = blockIdx.y;          // 0..15, covers tile-rows 2by, 2by+1
    int b  = blockIdx.z;
    int tid = threadIdx.x;
    int r_glob0 = 4 * by - 1;     // global image row of ds[0]

    for (int j = tid; j < 6 * 32 * 3; j += 256) {
        int colsel = j % 3;
        int rest = j / 3;
        int c = rest & 31, hi = rest >> 5;
        ds[hi][c][colsel == 0 ? 0 : 64 + colsel] = 0.f;
    }
    if (by == 0)
        for (int j = tid; j < 32 * 69; j += 256) ds[0][j / 69][j % 69] = 0.f;
    if (by == 15)
        for (int j = tid; j < 32 * 69; j += 256) ds[5][j / 69][j % 69] = 0.f;
    __syncthreads();

    int c_l = tid >> 3, q = tid & 7;        // c 0..31, 8-float segment
    int c = (cc << 5) + c_l;
    float sv = g_s[b * CC_TOT + c];
    const float* xp = x + ((size_t)(b * CC_TOT + c) << 12);
#pragma unroll
    for (int hi = 0; hi < 6; hi++) {
        int h = r_glob0 + hi;
        if ((unsigned)h < (unsigned)HH) {
            const float* row = xp + (h << 6) + (q << 3);
            float* dst = &ds[hi][c_l][1 + (q << 3)];
            float4 v0 = *(const float4*)row;
            float4 v1 = *(const float4*)(row + 4);
            dst[0] = v0.x * sv; dst[1] = v0.y * sv;
            dst[2] = v0.z * sv; dst[3] = v0.w * sv;
            dst[4] = v1.x * sv; dst[5] = v1.y * sv;
            dst[6] = v1.z * sv; dst[7] = v1.w * sv;
        }
    }
    __syncthreads();

    int wwarp = tid >> 5, lane = tid & 31;
    size_t cbase = (size_t)(cc << 5) + lane;
#pragma unroll
    for (int trr = 0; trr < 2; trr++) {
        int tilerow = 2 * by + trr;
#pragma unroll
        for (int itw = 0; itw < 4; itw++) {
            int tw = wwarp * 4 + itw;
            float d[4][4];
#pragma unroll
            for (int i = 0; i < 4; i++)
#pragma unroll
                for (int j = 0; j < 4; j++)
                    d[i][j] = ds[2 * trr + i][lane][2 * tw + j];
            float t[4][4];
#pragma unroll
            for (int j = 0; j < 4; j++) {
                t[0][j] = d[0][j] - d[2][j];
                t[1][j] = d[1][j] + d[2][j];
                t[2][j] = d[2][j] - d[1][j];
                t[3][j] = d[1][j] - d[3][j];
            }
            int tile = tilerow * 32 + tw;
#pragma unroll
            for (int i = 0; i < 4; i++) {
                float v0 = t[i][0] - t[i][2];
                float v1 = t[i][1] + t[i][2];
                float v2 = t[i][2] - t[i][1];
                float v3 = t[i][1] - t[i][3];
                int p = i * 4;
                g_V[((size_t)((p + 0) * 8 + b) * 1024 + tile) * CC_TOT + cbase] = __float2half(v0);
                g_V[((size_t)((p + 1) * 8 + b) * 1024 + tile) * CC_TOT + cbase] = __float2half(v1);
                g_V[((size_t)((p + 2) * 8 + b) * 1024 + tile) * CC_TOT + cbase] = __float2half(v2);
                g_V[((size_t)((p + 3) * 8 + b) * 1024 + tile) * CC_TOT + cbase] = __float2half(v3);
            }
        }
    }
}

// ---------------- batched GEMM: Mh[z] = U[z>>3] * V[z]^T ---------------------
// CTA 256 thr, tile 128x128, K=512 (16 chunks of 32), 4-stage single-barrier.
#define ROWB 80
#define ABUF 10240
#define NSTG 4
#define GSMEM (2 * NSTG * ABUF)   // 81920

__device__ __forceinline__ uint32_t smem_u32(const void* p) {
    uint32_t a;
    asm("{ .reg .u64 t; cvta.to.shared.u64 t, %1; cvt.u32.u64 %0, t; }"
        : "=r"(a) : "l"(p));
    return a;
}
#define CP_ASYNC16(dst, src) \
    asm volatile("cp.async.cg.shared.global [%0], [%1], 16;" \
                 :: "r"(dst), "l"(src) : "memory")
#define CP_COMMIT() asm volatile("cp.async.commit_group;" ::: "memory")
#define CP_WAIT(n)  asm volatile("cp.async.wait_group %0;" :: "n"(n) : "memory")
#define LDSM4(r0, r1, r2, r3, a) \
    asm volatile("ldmatrix.sync.aligned.m8n8.x4.shared.b16 {%0,%1,%2,%3}, [%4];" \
                 : "=r"(r0), "=r"(r1), "=r"(r2), "=r"(r3) : "r"(a))
#define MMA16816(d0, d1, d2, d3, a0, a1, a2, a3, b0, b1) \
    asm volatile("mma.sync.aligned.m16n8k16.row.col.f32.f16.f16.f32 " \
                 "{%0,%1,%2,%3}, {%4,%5,%6,%7}, {%8,%9}, {%0,%1,%2,%3};" \
                 : "+f"(d0), "+f"(d1), "+f"(d2), "+f"(d3) \
                 : "r"(a0), "r"(a1), "r"(a2), "r"(a3), "r"(b0), "r"(b1))

__global__ void __launch_bounds__(256, 2) wino_gemm_kernel() {
    extern __shared__ __align__(16) char sm[];   // A0..A3 B0..B3
    uint32_t smb = smem_u32(sm);

    int tid  = threadIdx.x;
    int wid  = tid >> 5;
    int lane = tid & 31;
    int warp_m = wid >> 2;            // 0..1 (64 o)
    int warp_n = wid & 3;             // 0..3 (32 tiles)

    int o_base = blockIdx.x * 128;
    int n_base = blockIdx.y * 128;
    int z      = blockIdx.z;          // p*8 + b

    const __half* Abase = g_U + ((size_t)(z >> 3) * OO + o_base) * CC_TOT;
    const __half* Bbase = g_V + ((size_t)z * 1024 + n_base) * CC_TOT;

    float acc[4][4][4];
#pragma unroll
    for (int i = 0; i < 4; i++)
#pragma unroll
        for (int j = 0; j < 4; j++)
#pragma unroll
            for (int k = 0; k < 4; k++) acc[i][j][k] = 0.f;

    int f_row = tid >> 1;
    auto issue = [&](int ch) {
        int buf = ch & (NSTG - 1);
        int c0 = ch << 5;
        uint32_t dA = smb + (uint32_t)buf * ABUF;
        uint32_t dB = smb + NSTG * ABUF + (uint32_t)buf * ABUF;
        const __half* sa = Abase + (size_t)f_row * CC_TOT + c0;
        const __half* sb = Bbase + (size_t)f_row * CC_TOT + c0;
#pragma unroll
        for (int u = 0; u < 2; u++) {
            int unit = (tid & 1) * 2 + u;
            CP_ASYNC16(dA + (uint32_t)(f_row * ROWB + unit * 16),
                       (const char*)(sa + unit * 8));
            CP_ASYNC16(dB + (uint32_t)(f_row * ROWB + unit * 16),
                       (const char*)(sb + unit * 8));
        }
        CP_COMMIT();
    };

    uint32_t a_off = (uint32_t)((warp_m * 64 + (lane & 15)) * ROWB + (lane >> 4) * 16);
    uint32_t b_off = (uint32_t)((warp_n * 32 + (lane & 15)) * ROWB + (lane >> 4) * 16);

    issue(0); issue(1); issue(2);

#pragma unroll 1
    for (int ch = 0; ch < 16; ch++) {
        // tail-safe waits: group `ch` must be complete before consuming buf.
        if (ch <= 13)      { CP_WAIT(2); }
        else if (ch == 14) { CP_WAIT(1); }
        else               { CP_WAIT(0); }
        __syncthreads();

        int buf = ch & (NSTG - 1);
        uint32_t sA = smb + (uint32_t)buf * ABUF;
        uint32_t sB = smb + NSTG * ABUF + (uint32_t)buf * ABUF;

#pragma unroll
        for (int ks = 0; ks < 2; ks++) {
            uint32_t koff = ks * 32;
            uint32_t a[4][4], bm[2][4];
#pragma unroll
            for (int mi = 0; mi < 4; mi++)
                LDSM4(a[mi][0], a[mi][1], a[mi][2], a[mi][3],
                      sA + a_off + (uint32_t)(mi * 16 * ROWB) + koff);
#pragma unroll
            for (int ni = 0; ni < 2; ni++)
                LDSM4(bm[ni][0], bm[ni][1], bm[ni][2], bm[ni][3],
                      sB + b_off + (uint32_t)(ni * 16 * ROWB) + koff);
#pragma unroll
            for (int mi = 0; mi < 4; mi++) {
#pragma unroll
                for (int ni = 0; ni < 2; ni++) {
                    MMA16816(acc[mi][ni * 2][0], acc[mi][ni * 2][1],
                             acc[mi][ni * 2][2], acc[mi][ni * 2][3],
                             a[mi][0], a[mi][1], a[mi][2], a[mi][3],
                             bm[ni][0], bm[ni][2]);
                    MMA16816(acc[mi][ni * 2 + 1][0], acc[mi][ni * 2 + 1][1],
                             acc[mi][ni * 2 + 1][2], acc[mi][ni * 2 + 1][3],
                             a[mi][0], a[mi][1], a[mi][2], a[mi][3],
                             bm[ni][1], bm[ni][3]);
                }
            }
        }
        // issue into buf (ch+3)&3 == (ch-1)&3: consumed last iteration,
        // all warps passed this iteration's barrier after reading it -> safe.
        if (ch + 3 < 16) issue(ch + 3);
    }

    // epilogue: write fp16 M
    __half* Mb = g_Mh + (size_t)z * OO * 1024;
#pragma unroll
    for (int mi = 0; mi < 4; mi++) {
#pragma unroll
        for (int hf = 0; hf < 2; hf++) {
            int o = o_base + warp_m * 64 + mi * 16 + (lane >> 2) + hf * 8;
            __half2* op = (__half2*)(Mb + (size_t)o * 1024 + n_base +
                                     warp_n * 32 + (lane & 3) * 2);
#pragma unroll
            for (int ni = 0; ni < 4; ni++)
                op[ni * 4] = __floats2half2_rn(acc[mi][ni][hf * 2 + 0],
                                               acc[mi][ni][hf * 2 + 1]);
        }
    }
}

// ---------------- output transform: out = A^T M A * demod --------------------
__global__ void __launch_bounds__(256) wino_out_kernel(float* __restrict__ out) {
    int bo = blockIdx.x;                 // b*512 + o
    int b = bo >> 9, o = bo & 511;
    int tid = threadIdx.x;
    float m = g_mult[bo];
    int t0 = tid << 2;                   // 4 tiles per thread

    float M4[16][4];
#pragma unroll
    for (int p = 0; p < 16; p++) {
        const __half2* src =
            (const __half2*)&g_Mh[((size_t)(p * 8 + b) * OO + o) * 1024 + t0];
        float2 f0 = __half22float2(src[0]);
        float2 f1 = __half22float2(src[1]);
        M4[p][0] = f0.x; M4[p][1] = f0.y; M4[p][2] = f1.x; M4[p][3] = f1.y;
    }

    int trr = t0 >> 5, tww = t0 & 31;
    float* op = out + (((size_t)bo) << 12) + (trr * 2) * 64 + tww * 2;
    float4 r0a, r0b, r1a, r1b;
#pragma unroll
    for (int j = 0; j < 4; j++) {
        float M[4][4];
#pragma unroll
        for (int p = 0; p < 16; p++)
            M[p >> 2][p & 3] = M4[p][j];
        float t0r[4], t1r[4];
#pragma unroll
        for (int k = 0; k < 4; k++) {
            t0r[k] = M[0][k] + M[1][k] + M[2][k];
            t1r[k] = M[1][k] - M[2][k] - M[3][k];
        }
        float y00 = (t0r[0] + t0r[1] + t0r[2]) * m;
        float y01 = (t0r[1] - t0r[2] - t0r[3]) * m;
        float y10 = (t1r[0] + t1r[1] + t1r[2]) * m;
        float y11 = (t1r[1] - t1r[2] - t1r[3]) * m;
        if (j < 2) {
            ((float2*)&r0a)[j] = make_float2(y00, y01);
            ((float2*)&r1a)[j] = make_float2(y10, y11);
        } else {
            ((float2*)&r0b)[j - 2] = make_float2(y00, y01);
            ((float2*)&r1b)[j - 2] = make_float2(y10, y11);
        }
    }
    *(float4*)op = r0a;
    *(float4*)(op + 4) = r0b;
    *(float4*)(op + 64) = r1a;
    *(float4*)(op + 68) = r1b;
}

// ---------------- launch -----------------------------------------------------
extern "C" void kernel_launch(void* const* d_in, const int* in_sizes, int n_in,
                              void* d_out, int out_size) {
    const float* input  = (const float*)d_in[0];   // [B,C,H,W]
    const float* style  = (const float*)d_in[1];   // [B,S]
    const float* weight = (const float*)d_in[2];   // [1,O,C,3,3]
    const float* mw     = (const float*)d_in[3];   // [C,S]
    const float* mb     = (const float*)d_in[4];   // [C]
    float* out = (float*)d_out;

    modw_kernel<<<512 + 1024, 256>>>(style, mw, mb, weight);
    demod_kernel<<<512, 256>>>();
    {
        dim3 gi(16, 16, 8);
        wino_in_kernel<<<gi, 256>>>(input);
    }
    cudaFuncSetAttribute(wino_gemm_kernel,
                         cudaFuncAttributeMaxDynamicSharedMemorySize, GSMEM);
    {
        dim3 gg(4, 8, 128);
        wino_gemm_kernel<<<gg, 256, GSMEM>>>();
    }
    wino_out_kernel<<<4096, 256>>>(out);
}